// round 14
// baseline (speedup 1.0000x reference)
#include <cuda_runtime.h>
#include <math.h>

#define NHID 1024
#define NOUT 50257
#define MAXLEN 24
#define NTILE ((NOUT + 7) / 8)      // 6283
#define NFIN 64
#define SLICE ((NOUT + NFIN - 1) / NFIN)   // 786

// -------- device scratch --------
__device__ float g_cat[2 * NHID];
__device__ float g_x[NHID];
__device__ float g_gh[3 * NHID];
__device__ float g_h[NHID];
__device__ float g_logits[NOUT];
__device__ float g_pm[NTILE];
__device__ float g_ps[NTILE];
__device__ unsigned g_tick2;        // k2 epoch counter (NTILE/epoch, never reset)

__device__ __forceinline__ float wredsum(float v) {
    #pragma unroll
    for (int o = 16; o; o >>= 1) v += __shfl_xor_sync(0xffffffffu, v, o);
    return v;
}
__device__ __forceinline__ float wredmax(float v) {
    #pragma unroll
    for (int o = 16; o; o >>= 1) v = fmaxf(v, __shfl_xor_sync(0xffffffffu, v, o));
    return v;
}
__device__ __forceinline__ float sigm(float x) { return 1.f / (1.f + expf(-x)); }
__device__ __forceinline__ float dot4(float4 a, float4 b) {
    return a.x * b.x + a.y * b.y + a.z * b.z + a.w * b.w;
}

// ========== kA: attention (block 0, may spill) | gh (blocks 1..384, lean) ==========
__global__ void __launch_bounds__(256, 6)
kA(const int* __restrict__ inp,
   const float* __restrict__ hidden,
   const float* __restrict__ enc_outs,
   const float* __restrict__ emb_W,
   const float* __restrict__ attn_W,
   const float* __restrict__ attn_b,
   const float* __restrict__ W_hh,
   const float* __restrict__ b_hh,
   float* __restrict__ attnw_out) {
    __shared__ float sv[2 * NHID];
    __shared__ float sscore[32];
    __shared__ float sw[MAXLEN];
    const int t = threadIdx.x, b = blockIdx.x;
    const int warp = t >> 5, lane = t & 31;
    float4* sv4 = (float4*)sv;

    if (b != 0) {
        // --- gh = W_hh @ h0 + b_hh : rows (b-1)*8+warp (lean path) ---
        sv4[t] = ((const float4*)hidden)[t];
        __syncthreads();
        int r = (b - 1) * 8 + warp;
        const float4* w = (const float4*)(W_hh + (size_t)r * NHID);
        float acc = 0.f;
        #pragma unroll
        for (int q = 0; q < 8; q++) {
            int idx = lane + 32 * q;
            acc += dot4(__ldcs(w + idx), sv4[idx]);
        }
        acc = wredsum(acc);
        if (lane == 0) g_gh[r] = acc + b_hh[r];
        return;
    }

    // --- attention (block 0 only; register spills OK) ---
    float4 ev = ((const float4*)(emb_W + (size_t)inp[0] * NHID))[t];
    sv4[t] = ev;
    ((float4*)g_cat)[t] = ev;
    sv4[256 + t] = ((const float4*)hidden)[t];
    __syncthreads();

    for (int r = warp; r < MAXLEN; r += 8) {
        const float4* w = (const float4*)(attn_W + (size_t)r * (2 * NHID));
        float acc = 0.f;
        #pragma unroll
        for (int q = 0; q < 16; q++) {
            int idx = lane + 32 * q;
            acc += dot4(w[idx], sv4[idx]);
        }
        acc = wredsum(acc);
        if (lane == 0) sscore[r] = acc + attn_b[r];
    }
    __syncthreads();

    if (warp == 0) {
        float v = (lane < MAXLEN) ? sscore[lane] : -INFINITY;
        float m = wredmax(v);
        float p = (lane < MAXLEN) ? expf(v - m) : 0.f;
        float s = wredsum(p);
        float wv = p / s;
        if (lane < MAXLEN) {
            sw[lane] = wv;
            attnw_out[lane] = wv;
        }
    }
    __syncthreads();

    {
        const float4* enc4 = (const float4*)enc_outs;
        float4 acc = make_float4(0.f, 0.f, 0.f, 0.f);
        #pragma unroll
        for (int m2 = 0; m2 < MAXLEN; m2++) {
            float wv = sw[m2];
            float4 v = enc4[m2 * 256 + t];
            acc.x += wv * v.x; acc.y += wv * v.y;
            acc.z += wv * v.z; acc.w += wv * v.w;
        }
        ((float4*)g_cat)[256 + t] = acc;
    }
}

// ========== kB: comb GEMV + relu (grid 128) ==========
__global__ void __launch_bounds__(256)
kB(const float* __restrict__ comb_W,
   const float* __restrict__ comb_b) {
    __shared__ float4 sc[512];
    const int t = threadIdx.x, b = blockIdx.x;
    const int warp = t >> 5, lane = t & 31;

    sc[t] = ((const float4*)g_cat)[t];
    sc[256 + t] = ((const float4*)g_cat)[256 + t];
    __syncthreads();

    int row = b * 8 + warp;
    const float4* w4 = (const float4*)(comb_W + (size_t)row * (2 * NHID));
    float acc = 0.f;
    #pragma unroll
    for (int k = 0; k < 16; k++) {
        int idx = lane + 32 * k;
        acc += dot4(__ldcs(w4 + idx), sc[idx]);
    }
    acc = wredsum(acc);
    if (lane == 0) g_x[row] = fmaxf(acc + comb_b[row], 0.f);
}

// ========== kC: gi + GRU gates (grid 128, warp per hidden unit) ==========
__global__ void __launch_bounds__(256)
kC(const float* __restrict__ W_ih,
   const float* __restrict__ b_ih,
   const float* __restrict__ hidden,
   float* __restrict__ hout) {
    __shared__ float4 sx[256];
    const int t = threadIdx.x, b = blockIdx.x;
    const int warp = t >> 5, lane = t & 31;

    sx[t] = ((const float4*)g_x)[t];
    __syncthreads();

    int k = b * 8 + warp;
    const float4* wir = (const float4*)(W_ih + (size_t)k * NHID);
    const float4* wiz = (const float4*)(W_ih + (size_t)(k + NHID) * NHID);
    const float4* win = (const float4*)(W_ih + (size_t)(k + 2 * NHID) * NHID);

    float air = 0.f, aiz = 0.f, ain = 0.f;
    #pragma unroll
    for (int q = 0; q < 8; q++) {
        int idx = lane + 32 * q;
        float4 x4 = sx[idx];
        air += dot4(__ldcs(wir + idx), x4);
        aiz += dot4(__ldcs(wiz + idx), x4);
        ain += dot4(__ldcs(win + idx), x4);
    }
    air = wredsum(air); aiz = wredsum(aiz); ain = wredsum(ain);

    if (lane == 0) {
        float r = sigm(air + b_ih[k] + g_gh[k]);
        float z = sigm(aiz + b_ih[NHID + k] + g_gh[NHID + k]);
        float n = tanhf(ain + b_ih[2 * NHID + k] + r * g_gh[2 * NHID + k]);
        float hnew = (1.f - z) * n + z * hidden[k];
        g_h[k] = hnew;
        hout[k] = hnew;
    }
}

// ========== k2: logits GEMV (grid 6283) + ticket epilogue ==========
__global__ void __launch_bounds__(256)
k2(const float* __restrict__ out_W,
   const float* __restrict__ out_b,
   float* __restrict__ logp) {
    __shared__ float4 sh[256];
    __shared__ float slog[8];
    __shared__ float sred[512];
    __shared__ unsigned s_pos, s_end;
    const int t = threadIdx.x, b = blockIdx.x;
    const int warp = t >> 5, lane = t & 31;

    sh[t] = ((const float4*)g_h)[t];
    __syncthreads();

    int row = b * 8 + warp;
    float y = -INFINITY;
    if (row < NOUT) {
        const float4* w = (const float4*)(out_W + (size_t)row * NHID);
        float acc = 0.f;
        #pragma unroll
        for (int k = 0; k < 8; k++) {
            int idx = lane + 32 * k;
            acc += dot4(__ldcs(w + idx), sh[idx]);
        }
        acc = wredsum(acc);
        if (lane == 0) {
            y = acc + out_b[row];
            g_logits[row] = y;
        }
    }
    if (lane == 0) slog[warp] = y;
    __syncthreads();

    if (warp == 0) {
        float v = (lane < 8) ? slog[lane] : -INFINITY;
        float m = wredmax(v);
        float e = (lane < 8 && v > -INFINITY) ? __expf(v - m) : 0.f;
        e = wredsum(e);
        if (lane == 0) {
            g_pm[b] = m;
            g_ps[b] = e;
        }
    }
    __syncthreads();

    // ---- epoch ticket ----
    if (t == 0) {
        __threadfence();
        unsigned old = atomicAdd(&g_tick2, 1u);
        s_pos = old % NTILE;
        s_end = old - s_pos + NTILE;
    }
    __syncthreads();
    unsigned pos = s_pos;
    if (pos < NTILE - NFIN) return;

    if (t == 0) {
        volatile unsigned* p = &g_tick2;
        while (*p < s_end) { __nanosleep(64); }
        __threadfence();
    }
    __syncthreads();

    float m = -INFINITY, s = 0.f;
    for (int i = t; i < NTILE; i += 256) {
        float mb = g_pm[i], sb = g_ps[i];
        if (mb > m) { s = s * __expf(m - mb) + sb; m = mb; }
        else        { s += sb * __expf(mb - m); }
    }
    sred[t] = m; sred[256 + t] = s;
    __syncthreads();
    for (int o = 128; o; o >>= 1) {
        if (t < o) {
            float m1 = sred[t], s1 = sred[256 + t];
            float m2 = sred[t + o], s2 = sred[256 + t + o];
            float M = fmaxf(m1, m2);
            float S = (s1 > 0.f ? s1 * __expf(m1 - M) : 0.f) +
                      (s2 > 0.f ? s2 * __expf(m2 - M) : 0.f);
            sred[t] = M; sred[256 + t] = S;
        }
        __syncthreads();
    }
    float C = sred[0] + logf(sred[256]);

    int idx = (int)(pos - (NTILE - NFIN));
    int lo = idx * SLICE;
    int hi = min(lo + SLICE, NOUT);
    for (int i = lo + t; i < hi; i += 256)
        logp[i] = g_logits[i] - C;
}

extern "C" void kernel_launch(void* const* d_in, const int* in_sizes, int n_in,
                              void* d_out, int out_size) {
    const int*   inp      = (const int*)  d_in[0];
    const float* hidden   = (const float*)d_in[1];
    const float* enc_outs = (const float*)d_in[3];
    const float* emb_W    = (const float*)d_in[4];
    const float* attn_W   = (const float*)d_in[5];
    const float* attn_b   = (const float*)d_in[6];
    const float* comb_W   = (const float*)d_in[7];
    const float* comb_b   = (const float*)d_in[8];
    const float* W_ih     = (const float*)d_in[9];
    const float* W_hh     = (const float*)d_in[10];
    const float* b_ih     = (const float*)d_in[11];
    const float* b_hh     = (const float*)d_in[12];
    const float* out_W    = (const float*)d_in[13];
    const float* out_b    = (const float*)d_in[14];

    float* out   = (float*)d_out;
    float* logp  = out;                 // [50257]
    float* hout  = out + NOUT;          // [1024]
    float* attnw = out + NOUT + NHID;   // [24]

    kA<<<385, 256>>>(inp, hidden, enc_outs, emb_W, attn_W, attn_b,
                     W_hh, b_hh, attnw);
    kB<<<128, 256>>>(comb_W, comb_b);
    kC<<<128, 256>>>(W_ih, b_ih, hidden, hout);
    k2<<<NTILE, 256>>>(out_W, out_b, logp);
}

// round 15
// speedup vs baseline: 1.0919x; 1.0919x over previous
#include <cuda_runtime.h>
#include <math.h>

#define NHID 1024
#define NOUT 50257
#define MAXLEN 24
#define NTILE ((NOUT + 7) / 8)      // 6283
#define NFIN 64
#define SLICE ((NOUT + NFIN - 1) / NFIN)   // 786

// -------- device scratch --------
__device__ float g_cat[2 * NHID];
__device__ float g_x[NHID];
__device__ float g_gh[3 * NHID];
__device__ float g_h[NHID];
__device__ float g_logits[NOUT];
__device__ float g_pm[NTILE];
__device__ float g_ps[NTILE];
__device__ unsigned g_sync1;        // K1 comb-group entry ticket (128/launch)
__device__ unsigned g_att;          // attention-done counter (1/launch)
__device__ unsigned g_tick2;        // k2 epilogue ticket (NTILE/launch)

__device__ __forceinline__ float wredsum(float v) {
    #pragma unroll
    for (int o = 16; o; o >>= 1) v += __shfl_xor_sync(0xffffffffu, v, o);
    return v;
}
__device__ __forceinline__ float wredmax(float v) {
    #pragma unroll
    for (int o = 16; o; o >>= 1) v = fmaxf(v, __shfl_xor_sync(0xffffffffu, v, o));
    return v;
}
__device__ __forceinline__ float sigm(float x) { return 1.f / (1.f + expf(-x)); }
__device__ __forceinline__ float dot4(float4 a, float4 b) {
    return a.x * b.x + a.y * b.y + a.z * b.z + a.w * b.w;
}

// ========== K1: gh (blocks 0..383) | attention-once + comb (blocks 384..511) ==========
__global__ void __launch_bounds__(256, 4)
K1(const int* __restrict__ inp,
   const float* __restrict__ hidden,
   const float* __restrict__ enc_outs,
   const float* __restrict__ emb_W,
   const float* __restrict__ attn_W,
   const float* __restrict__ attn_b,
   const float* __restrict__ comb_W,
   const float* __restrict__ comb_b,
   const float* __restrict__ W_hh,
   const float* __restrict__ b_hh,
   float* __restrict__ attnw_out) {
    __shared__ float sv[2 * NHID];
    __shared__ float sscore[32];
    __shared__ float sw[MAXLEN];
    __shared__ unsigned s_e;
    __shared__ int s_first;
    const int t = threadIdx.x, b = blockIdx.x;
    const int warp = t >> 5, lane = t & 31;
    float4* sv4 = (float4*)sv;

    if (b < 384) {
        // ---- lean gh path: gh = W_hh @ h0 + b_hh ----
        sv4[t] = ((const float4*)hidden)[t];
        __syncthreads();
        int r = b * 8 + warp;
        const float4* w = (const float4*)(W_hh + (size_t)r * NHID);
        float acc = 0.f;
        #pragma unroll
        for (int q = 0; q < 8; q++) {
            int idx = lane + 32 * q;
            acc += dot4(__ldcs(w + idx), sv4[idx]);
        }
        acc = wredsum(acc);
        if (lane == 0) g_gh[r] = acc + b_hh[r];
        return;
    }

    // ---- comb group (128 blocks): entry ticket picks the attention performer ----
    if (t == 0) {
        unsigned old = atomicAdd(&g_sync1, 1u);
        s_e = old / 128u;                 // launch epoch
        s_first = (old % 128u == 0u);
    }
    __syncthreads();

    if (s_first) {
        // --- attention, computed once (modest unrolls: keep regs low) ---
        float4 ev = ((const float4*)(emb_W + (size_t)inp[0] * NHID))[t];
        sv4[t] = ev;
        ((float4*)g_cat)[t] = ev;
        sv4[256 + t] = ((const float4*)hidden)[t];
        __syncthreads();

        for (int r = warp; r < MAXLEN; r += 8) {
            const float4* w = (const float4*)(attn_W + (size_t)r * (2 * NHID));
            float acc = 0.f;
            #pragma unroll 4
            for (int q = 0; q < 16; q++) {
                int idx = lane + 32 * q;
                acc += dot4(w[idx], sv4[idx]);
            }
            acc = wredsum(acc);
            if (lane == 0) sscore[r] = acc + attn_b[r];
        }
        __syncthreads();

        if (warp == 0) {
            float v = (lane < MAXLEN) ? sscore[lane] : -INFINITY;
            float m = wredmax(v);
            float p = (lane < MAXLEN) ? expf(v - m) : 0.f;
            float s = wredsum(p);
            float wv = p / s;
            if (lane < MAXLEN) {
                sw[lane] = wv;
                attnw_out[lane] = wv;
            }
        }
        __syncthreads();

        {
            const float4* enc4 = (const float4*)enc_outs;
            float4 acc = make_float4(0.f, 0.f, 0.f, 0.f);
            #pragma unroll 4
            for (int m2 = 0; m2 < MAXLEN; m2++) {
                float wv = sw[m2];
                float4 v = enc4[m2 * 256 + t];
                acc.x += wv * v.x; acc.y += wv * v.y;
                acc.z += wv * v.z; acc.w += wv * v.w;
            }
            ((float4*)g_cat)[256 + t] = acc;
        }
        __syncthreads();
        if (t == 0) {
            __threadfence();
            atomicAdd(&g_att, 1u);
        }
    }

    // ---- all comb blocks wait for attention of this epoch ----
    if (t == 0) {
        volatile unsigned* p = &g_att;
        while (*p < s_e + 1u) { __nanosleep(32); }
        __threadfence();
    }
    __syncthreads();

    // ---- comb GEMV + relu ----
    sv4[t] = ((const float4*)g_cat)[t];
    sv4[256 + t] = ((const float4*)g_cat)[256 + t];
    __syncthreads();

    int row = (b - 384) * 8 + warp;
    const float4* w4 = (const float4*)(comb_W + (size_t)row * (2 * NHID));
    float acc = 0.f;
    #pragma unroll 8
    for (int k = 0; k < 16; k++) {
        int idx = lane + 32 * k;
        acc += dot4(__ldcs(w4 + idx), sv4[idx]);
    }
    acc = wredsum(acc);
    if (lane == 0) g_x[row] = fmaxf(acc + comb_b[row], 0.f);
}

// ========== kC: gi + GRU gates (grid 128, warp per hidden unit) ==========
__global__ void __launch_bounds__(256, 4)
kC(const float* __restrict__ W_ih,
   const float* __restrict__ b_ih,
   const float* __restrict__ hidden,
   float* __restrict__ hout) {
    __shared__ float4 sx[256];
    const int t = threadIdx.x, b = blockIdx.x;
    const int warp = t >> 5, lane = t & 31;

    sx[t] = ((const float4*)g_x)[t];
    __syncthreads();

    int k = b * 8 + warp;
    const float4* wir = (const float4*)(W_ih + (size_t)k * NHID);
    const float4* wiz = (const float4*)(W_ih + (size_t)(k + NHID) * NHID);
    const float4* win = (const float4*)(W_ih + (size_t)(k + 2 * NHID) * NHID);

    float air = 0.f, aiz = 0.f, ain = 0.f;
    #pragma unroll
    for (int q = 0; q < 8; q++) {
        int idx = lane + 32 * q;
        float4 x4 = sx[idx];
        air += dot4(__ldcs(wir + idx), x4);
        aiz += dot4(__ldcs(wiz + idx), x4);
        ain += dot4(__ldcs(win + idx), x4);
    }
    air = wredsum(air); aiz = wredsum(aiz); ain = wredsum(ain);

    if (lane == 0) {
        float r = sigm(air + b_ih[k] + g_gh[k]);
        float z = sigm(aiz + b_ih[NHID + k] + g_gh[NHID + k]);
        float n = tanhf(ain + b_ih[2 * NHID + k] + r * g_gh[2 * NHID + k]);
        float hnew = (1.f - z) * n + z * hidden[k];
        g_h[k] = hnew;
        hout[k] = hnew;
    }
}

// ========== k2: logits GEMV (grid 6283, 6 blocks/SM => regs cap 42) + ticket epilogue ==========
__global__ void __launch_bounds__(256, 6)
k2(const float* __restrict__ out_W,
   const float* __restrict__ out_b,
   float* __restrict__ logp) {
    __shared__ float4 sh[256];
    __shared__ float slog[8];
    __shared__ float sred[512];
    __shared__ unsigned s_pos, s_end;
    const int t = threadIdx.x, b = blockIdx.x;
    const int warp = t >> 5, lane = t & 31;

    sh[t] = ((const float4*)g_h)[t];
    __syncthreads();

    int row = b * 8 + warp;
    float y = -INFINITY;
    if (row < NOUT) {
        const float4* w = (const float4*)(out_W + (size_t)row * NHID);
        float acc = 0.f;
        #pragma unroll
        for (int k = 0; k < 8; k++) {
            int idx = lane + 32 * k;
            acc += dot4(__ldcs(w + idx), sh[idx]);
        }
        acc = wredsum(acc);
        if (lane == 0) {
            y = acc + out_b[row];
            g_logits[row] = y;
        }
    }
    if (lane == 0) slog[warp] = y;
    __syncthreads();

    if (warp == 0) {
        float v = (lane < 8) ? slog[lane] : -INFINITY;
        float m = wredmax(v);
        float e = (lane < 8 && v > -INFINITY) ? __expf(v - m) : 0.f;
        e = wredsum(e);
        if (lane == 0) {
            g_pm[b] = m;
            g_ps[b] = e;
        }
    }
    __syncthreads();

    // ---- epoch ticket ----
    if (t == 0) {
        __threadfence();
        unsigned old = atomicAdd(&g_tick2, 1u);
        s_pos = old % NTILE;
        s_end = old - s_pos + NTILE;
    }
    __syncthreads();
    unsigned pos = s_pos;
    if (pos < NTILE - NFIN) return;

    if (t == 0) {
        volatile unsigned* p = &g_tick2;
        while (*p < s_end) { __nanosleep(64); }
        __threadfence();
    }
    __syncthreads();

    float m = -INFINITY, s = 0.f;
    for (int i = t; i < NTILE; i += 256) {
        float mb = g_pm[i], sb = g_ps[i];
        if (mb > m) { s = s * __expf(m - mb) + sb; m = mb; }
        else        { s += sb * __expf(mb - m); }
    }
    sred[t] = m; sred[256 + t] = s;
    __syncthreads();
    for (int o = 128; o; o >>= 1) {
        if (t < o) {
            float m1 = sred[t], s1 = sred[256 + t];
            float m2 = sred[t + o], s2 = sred[256 + t + o];
            float M = fmaxf(m1, m2);
            float S = (s1 > 0.f ? s1 * __expf(m1 - M) : 0.f) +
                      (s2 > 0.f ? s2 * __expf(m2 - M) : 0.f);
            sred[t] = M; sred[256 + t] = S;
        }
        __syncthreads();
    }
    float C = sred[0] + logf(sred[256]);

    int idx = (int)(pos - (NTILE - NFIN));
    int lo = idx * SLICE;
    int hi = min(lo + SLICE, NOUT);
    for (int i = lo + t; i < hi; i += 256)
        logp[i] = g_logits[i] - C;
}

extern "C" void kernel_launch(void* const* d_in, const int* in_sizes, int n_in,
                              void* d_out, int out_size) {
    const int*   inp      = (const int*)  d_in[0];
    const float* hidden   = (const float*)d_in[1];
    const float* enc_outs = (const float*)d_in[3];
    const float* emb_W    = (const float*)d_in[4];
    const float* attn_W   = (const float*)d_in[5];
    const float* attn_b   = (const float*)d_in[6];
    const float* comb_W   = (const float*)d_in[7];
    const float* comb_b   = (const float*)d_in[8];
    const float* W_ih     = (const float*)d_in[9];
    const float* W_hh     = (const float*)d_in[10];
    const float* b_ih     = (const float*)d_in[11];
    const float* b_hh     = (const float*)d_in[12];
    const float* out_W    = (const float*)d_in[13];
    const float* out_b    = (const float*)d_in[14];

    float* out   = (float*)d_out;
    float* logp  = out;                 // [50257]
    float* hout  = out + NOUT;          // [1024]
    float* attnw = out + NOUT + NHID;   // [24]

    K1<<<512, 256>>>(inp, hidden, enc_outs, emb_W, attn_W, attn_b,
                     comb_W, comb_b, W_hh, b_hh, attnw);
    kC<<<128, 256>>>(W_ih, b_ih, hidden, hout);
    k2<<<NTILE, 256>>>(out_W, out_b, logp);
}